// round 15
// baseline (speedup 1.0000x reference)
#include <cuda_runtime.h>
#include <cuda_fp16.h>
#include <cstdint>
#include <cstddef>

// Problem dims
#define BDIM 4096
#define HDIM 1024
#define NDIM 6144           // 6 gates * H (gate-interleaved: n' = h*6 + gate)
#define KTOT 2048           // joint K (x|h concatenated)

// GEMM tiling: CTA 128x96 (16 h-cols x 6 gates), 8 warps of 64x24, 2 CTAs/SM
#define BM 128
#define BN 96
#define BK 32               // halves per k-chunk = 64B rows (conflict-free LDS.128)
#define ROWB 64
#define A_TILE_BYTES (128 * ROWB)        // 8192
#define B_TILE_BYTES (96 * ROWB)         // 6144
#define STAGE_BYTES (A_TILE_BYTES + B_TILE_BYTES)   // 14336
#define NSTAGE 4
#define NK 64               // 2048 / 32
#define PIPE_OFF 512
#define ZST 132             // zs row stride (floats) — conflict-free STS
#define EPI_BYTES ((96 + 16) * ZST * 4)  // 59136
#define SMEM_TOTAL (PIPE_OFF + (EPI_BYTES > NSTAGE*STAGE_BYTES ? EPI_BYTES : NSTAGE*STAGE_BYTES))

// Scratch
__device__ __half g_Ah[(size_t)BDIM * KTOT];   // [x | h] fp16
__device__ __half g_Bh[(size_t)NDIM * KTOT];   // gate-interleaved [W | U] fp16

__device__ __forceinline__ void cp_async16(uint32_t smem_addr, const void* gmem_ptr) {
    asm volatile("cp.async.cg.shared.global [%0], [%1], 16;\n" :: "r"(smem_addr), "l"(gmem_ptr));
}

__device__ __forceinline__ float sigmoidf_(float z) { return 1.0f / (1.0f + expf(-z)); }

// ---------------- merged fp32 -> fp16 conversion (grid-stride) ----------------
#define QX (BDIM * 256)
#define QW (NDIM * 256)
__global__ __launch_bounds__(256)
void conv_all_kernel(const float* __restrict__ x, const float* __restrict__ h,
                     const float* __restrict__ W, const float* __restrict__ Uu,
                     __half* __restrict__ Ah, __half* __restrict__ Bh) {
    const int total = 2 * QX + 2 * QW;
    for (int q = blockIdx.x * blockDim.x + threadIdx.x; q < total;
         q += gridDim.x * blockDim.x) {
        const float* src;
        __half* dst;
        int local, koff;
        bool interleave;
        if (q < 2 * QX) {
            dst = Ah; interleave = false;
            if (q < QX) { src = x; local = q; koff = 0; }
            else        { src = h; local = q - QX; koff = 1024; }
        } else {
            int r = q - 2 * QX;
            dst = Bh; interleave = true;
            if (r < QW) { src = W;  local = r; koff = 0; }
            else        { src = Uu; local = r - QW; koff = 1024; }
        }
        int row = local >> 8;
        int c   = (local & 255) * 4;
        float4 v = *(const float4*)&src[(size_t)row * 1024 + c];
        __half2 h0 = __floats2half2_rn(v.x, v.y);
        __half2 h1 = __floats2half2_rn(v.z, v.w);
        uint2 packed = make_uint2(*(uint32_t*)&h0, *(uint32_t*)&h1);
        int drow = row;
        if (interleave) {                       // src row n = gate*1024 + hcol
            int gate = row >> 10, hcol = row & 1023;
            drow = hcol * 6 + gate;             // n' = h*6 + gate
        }
        *(uint2*)&dst[(size_t)drow * KTOT + koff + c] = packed;
    }
}

// ------------- fused GEMM (split-K fp16-accum, K=64 chunks -> fp32) + gate epilogue -------------
__global__ __launch_bounds__(256, 2)
void xlstm_fused_kernel(const __half* __restrict__ A, const __half* __restrict__ B,
                        const float* __restrict__ c_prev, const float* __restrict__ b_all,
                        float* __restrict__ out) {
    extern __shared__ char smem[];
    const uint32_t sbase = (uint32_t)__cvta_generic_to_shared(smem);

    const int tid  = threadIdx.x;
    const int warp = tid >> 5;
    const int lane = tid & 31;
    const int wm = warp & 1;        // 2 warps along M (64 rows)
    const int wn = warp >> 1;       // 4 warps along N (24 cols)
    const int g  = lane >> 2;       // 0..7
    const int tg = lane & 3;        // 0..3

    const int bm = blockIdx.y * BM;
    const int bnp = blockIdx.x * BN;     // interleaved-col offset
    const int h0 = blockIdx.x * 16;      // h block base

    const int lr = tid >> 1;        // 0..127
    const int lch = tid & 1;

    float acc[4][3][4];             // fp32 master accumulators
    uint32_t hacc[4][3][2];         // fp16x2 chunk accumulators (K=64 chain)
    float wx4[4][2];
    #pragma unroll
    for (int mf = 0; mf < 4; mf++) {
        wx4[mf][0] = wx4[mf][1] = 0.0f;
        #pragma unroll
        for (int nf = 0; nf < 3; nf++) {
            hacc[mf][nf][0] = hacc[mf][nf][1] = 0u;
            #pragma unroll
            for (int r = 0; r < 4; r++) acc[mf][nf][r] = 0.0f;
        }
    }

    auto load_stage = [&](int i, int s) {
        const int k0 = i * BK;
        const uint32_t as = sbase + PIPE_OFF + s * STAGE_BYTES;
        const uint32_t bs = as + A_TILE_BYTES;
        const __half* ap = A + (size_t)(bm + lr) * KTOT + k0 + lch * 8;
        cp_async16(as + lr * ROWB + lch * 16,      ap);
        cp_async16(as + lr * ROWB + lch * 16 + 32, ap + 16);
        {   // B chunk tid (rows 0..63)
            int row = tid >> 2, ch = tid & 3;
            cp_async16(bs + row * ROWB + ch * 16,
                       B + (size_t)(bnp + row) * KTOT + k0 + ch * 8);
        }
        if (tid < 128) {   // B chunk tid+256 (rows 64..95)
            int cb = tid + 256;
            int row = cb >> 2, ch = cb & 3;
            cp_async16(bs + row * ROWB + ch * 16,
                       B + (size_t)(bnp + row) * KTOT + k0 + ch * 8);
        }
        asm volatile("cp.async.commit_group;\n" ::: "memory");
    };

    // One pipeline iteration (s/waitn/doload/fold are compile-time literals at call sites).
    // MMAs chain in fp16 accumulation; every 2nd iter (fold=true, K=64 chunk) the fp16
    // partials are folded into the fp32 master accumulators and reset.
    auto iter = [&](int i, int s, int waitn, bool doload, bool fold) {
        if (waitn == 2)      asm volatile("cp.async.wait_group 2;\n" ::: "memory");
        else if (waitn == 1) asm volatile("cp.async.wait_group 1;\n" ::: "memory");
        else                 asm volatile("cp.async.wait_group 0;\n" ::: "memory");
        __syncthreads();

        if (doload) load_stage(i + 3, (i + 3) & 3);

        const uint4* as4 = (const uint4*)(smem + PIPE_OFF + s * STAGE_BYTES);
        const uint4* bs4 = (const uint4*)(smem + PIPE_OFF + s * STAGE_BYTES + A_TILE_BYTES);

        // k-remap: thread tg owns halves [8tg,8tg+8); (x,y) -> k16-step0 slots,
        // (z,w) -> step1. Same map for A and B => dot products unchanged.
        uint4 bq[3];
        #pragma unroll
        for (int nf = 0; nf < 3; nf++) {
            int c0 = wn * 24 + nf * 8 + g;
            bq[nf] = bs4[c0 * 4 + tg];
        }
        #pragma unroll
        for (int mf = 0; mf < 4; mf++) {
            int rr = wm * 64 + mf * 16 + g;
            uint4 lo = as4[rr * 4 + tg];
            uint4 hi = as4[(rr + 8) * 4 + tg];
            #pragma unroll
            for (int nf = 0; nf < 3; nf++) {
                asm volatile(
                    "mma.sync.aligned.m16n8k16.row.col.f16.f16.f16.f16 "
                    "{%0,%1}, {%2,%3,%4,%5}, {%6,%7}, {%0,%1};\n"
                    : "+r"(hacc[mf][nf][0]), "+r"(hacc[mf][nf][1])
                    : "r"(lo.x), "r"(hi.x), "r"(lo.y), "r"(hi.y),
                      "r"(bq[nf].x), "r"(bq[nf].y));
            }
            #pragma unroll
            for (int nf = 0; nf < 3; nf++) {
                asm volatile(
                    "mma.sync.aligned.m16n8k16.row.col.f16.f16.f16.f16 "
                    "{%0,%1}, {%2,%3,%4,%5}, {%6,%7}, {%0,%1};\n"
                    : "+r"(hacc[mf][nf][0]), "+r"(hacc[mf][nf][1])
                    : "r"(lo.z), "r"(hi.z), "r"(lo.w), "r"(hi.w),
                      "r"(bq[nf].z), "r"(bq[nf].w));
            }
        }

        if (fold) {
            #pragma unroll
            for (int mf = 0; mf < 4; mf++)
                #pragma unroll
                for (int nf = 0; nf < 3; nf++) {
                    float2 p0 = __half22float2(*(__half2*)&hacc[mf][nf][0]);
                    float2 p1 = __half22float2(*(__half2*)&hacc[mf][nf][1]);
                    acc[mf][nf][0] += p0.x;
                    acc[mf][nf][1] += p0.y;
                    acc[mf][nf][2] += p1.x;
                    acc[mf][nf][3] += p1.y;
                    hacc[mf][nf][0] = 0u;
                    hacc[mf][nf][1] = 0u;
                }
        }
    };

    load_stage(0, 0);
    load_stage(1, 1);
    load_stage(2, 2);

    const int nf4 = (2 - tg + 3) % 3;    // the nf whose col-pair is (gate4, gate5)

    // First K half (x*W): i = 0..31; fold every 2nd iter (K=64 chunks)
    #pragma unroll 1
    for (int ib = 0; ib < 32; ib += 4) {
        iter(ib + 0, 0, 2, true,  false);
        iter(ib + 1, 1, 2, true,  true);
        iter(ib + 2, 2, 2, true,  false);
        iter(ib + 3, 3, 2, true,  true);
    }

    // Midpoint (fold at i=31 completed the x*W half): save gate-4 (wx4), reset.
    #pragma unroll
    for (int nf = 0; nf < 3; nf++) {
        if (nf == nf4) {
            #pragma unroll
            for (int mf = 0; mf < 4; mf++) {
                wx4[mf][0] = acc[mf][nf][0];
                wx4[mf][1] = acc[mf][nf][2];
                acc[mf][nf][0] = 0.0f;
                acc[mf][nf][2] = 0.0f;
            }
        }
    }

    // Second K half (h*U): i = 32..59 grouped, 60..63 peeled
    #pragma unroll 1
    for (int ib = 32; ib < 60; ib += 4) {
        iter(ib + 0, 0, 2, true,  false);
        iter(ib + 1, 1, 2, true,  true);
        iter(ib + 2, 2, 2, true,  false);
        iter(ib + 3, 3, 2, true,  true);
    }
    iter(60, 0, 2, true,  false);   // loads stage for i=63
    iter(61, 1, 2, false, true);
    iter(62, 2, 1, false, false);
    iter(63, 3, 0, false, true);

    // -------- prefetch epilogue operands (overlap DRAM latency with smem exchange) --------
    const int hl   = tid & 15;
    const int bgrp = tid >> 4;             // 0..15, 8 rows each
    const int hg   = h0 + hl;
    float cpre[8];
    #pragma unroll
    for (int r = 0; r < 8; r++)
        cpre[r] = c_prev[(size_t)(bm + bgrp * 8 + r) * HDIM + hg];
    const float b0 = b_all[hg];
    const float b1 = b_all[1024 + hg];
    const float b2 = b_all[2048 + hg];
    const float b3 = b_all[3072 + hg];
    const float b4 = b_all[4096 + hg];
    const float b5 = b_all[5120 + hg];

    // -------- in-CTA gate epilogue --------
    __syncthreads();                       // all LDS of final stage consumed
    float* zs   = (float*)(smem + PIPE_OFF);        // [96][ZST]
    float* wx4s = zs + 96 * ZST;                    // [16][ZST]

    // h-local index of this thread's gate-4 column:
    // c = wn*24 + nf4*8 + 2tg  ->  h_local = wn*4 + (nf4*8 + 2tg)/6
    const int hl4 = wn * 4 + (nf4 * 8 + 2 * tg) / 6;

    #pragma unroll
    for (int mf = 0; mf < 4; mf++) {
        int row = wm * 64 + mf * 16 + g;
        #pragma unroll
        for (int nf = 0; nf < 3; nf++) {
            int col = wn * 24 + nf * 8 + 2 * tg;
            zs[col * ZST + row]           = acc[mf][nf][0];
            zs[(col + 1) * ZST + row]     = acc[mf][nf][1];
            zs[col * ZST + row + 8]       = acc[mf][nf][2];
            zs[(col + 1) * ZST + row + 8] = acc[mf][nf][3];
        }
        wx4s[hl4 * ZST + row]     = wx4[mf][0];
        wx4s[hl4 * ZST + row + 8] = wx4[mf][1];
    }
    __syncthreads();

    #pragma unroll
    for (int r = 0; r < 8; r++) {
        int b = bgrp * 8 + r;
        int bg = bm + b;
        float z0 = zs[(hl * 6 + 0) * ZST + b] + b0;
        float z1 = zs[(hl * 6 + 1) * ZST + b] + b1;
        float z2 = zs[(hl * 6 + 2) * ZST + b] + b2;
        float z3 = zs[(hl * 6 + 3) * ZST + b] + b3;
        float u4 = zs[(hl * 6 + 4) * ZST + b];          // uh4 (second half only)
        float z5 = zs[(hl * 6 + 5) * ZST + b] + b5;
        float w4 = wx4s[hl * ZST + b] + b4;             // wx4 + bias

        float ig = sigmoidf_(z0);
        float fg = sigmoidf_(z1);
        float og = sigmoidf_(z2);
        float gg = tanhf(z3);
        float m  = w4 * u4;
        float ag = sigmoidf_(z5);

        float cn = fg * cpre[r] + ig * gg + ag * m;
        float hn = og * tanhf(cn);

        out[(size_t)bg * HDIM + hg] = hn;
        out[(size_t)BDIM * HDIM + (size_t)bg * HDIM + hg] = cn;
    }
}

extern "C" void kernel_launch(void* const* d_in, const int* in_sizes, int n_in,
                              void* d_out, int out_size) {
    const float* x      = (const float*)d_in[0];
    const float* h_prev = (const float*)d_in[1];
    const float* c_prev = (const float*)d_in[2];
    const float* W_all  = (const float*)d_in[3];
    const float* b_all  = (const float*)d_in[4];
    const float* U_all  = (const float*)d_in[5];
    float* out = (float*)d_out;

    __half *pAh = nullptr, *pBh = nullptr;
    cudaGetSymbolAddress((void**)&pAh, g_Ah);
    cudaGetSymbolAddress((void**)&pBh, g_Bh);

    // Grid-stride conversion, exact-fill launch (8 CTAs/SM x 148 SMs)
    conv_all_kernel<<<1184, 256>>>(x, h_prev, W_all, U_all, pAh, pBh);

    cudaFuncSetAttribute(xlstm_fused_kernel,
                         cudaFuncAttributeMaxDynamicSharedMemorySize, SMEM_TOTAL);

    dim3 grid(HDIM / 16, BDIM / BM);   // 64 x 32
    xlstm_fused_kernel<<<grid, 256, SMEM_TOTAL>>>(pAh, pBh, c_prev, b_all, out);
}

// round 16
// speedup vs baseline: 1.2704x; 1.2704x over previous
#include <cuda_runtime.h>
#include <cuda_fp16.h>
#include <cstdint>
#include <cstddef>

// Problem dims
#define BDIM 4096
#define HDIM 1024
#define NDIM 6144           // 6 gates * H (gate-interleaved: n' = h*6 + gate)
#define KTOT 2048           // joint K (x|h concatenated)

// GEMM tiling: CTA 128x96 (16 h-cols x 6 gates), 8 warps of 64x24, 2 CTAs/SM
#define BM 128
#define BN 96
#define BK 32               // halves per k-chunk = 64B rows (conflict-free LDS.128)
#define ROWB 64
#define A_TILE_BYTES (128 * ROWB)        // 8192
#define B_TILE_BYTES (96 * ROWB)         // 6144
#define STAGE_BYTES (A_TILE_BYTES + B_TILE_BYTES)   // 14336
#define NSTAGE 4
#define NK 64               // 2048 / 32
#define PIPE_OFF 512
#define ZST 132             // zs row stride (floats) — conflict-free STS
#define EPI_BYTES ((96 + 16) * ZST * 4)  // 59136
#define SMEM_TOTAL (PIPE_OFF + (EPI_BYTES > NSTAGE*STAGE_BYTES ? EPI_BYTES : NSTAGE*STAGE_BYTES))

// Scratch
__device__ __half g_Ah[(size_t)BDIM * KTOT];   // [x | h] fp16
__device__ __half g_Bh[(size_t)NDIM * KTOT];   // gate-interleaved [W | U] fp16

__device__ __forceinline__ void cp_async16(uint32_t smem_addr, const void* gmem_ptr) {
    asm volatile("cp.async.cg.shared.global [%0], [%1], 16;\n" :: "r"(smem_addr), "l"(gmem_ptr));
}

__device__ __forceinline__ float sigmoidf_(float z) { return 1.0f / (1.0f + expf(-z)); }

// ---------------- merged fp32 -> fp16 conversion (grid-stride, streaming hints) ----------------
// x -> Ah[:,0:1024], h -> Ah[:,1024:], W -> Bh[h*6+g, 0:1024], U -> Bh[h*6+g, 1024:]
#define QX (BDIM * 256)
#define QW (NDIM * 256)
__global__ __launch_bounds__(256)
void conv_all_kernel(const float* __restrict__ x, const float* __restrict__ h,
                     const float* __restrict__ W, const float* __restrict__ Uu,
                     __half* __restrict__ Ah, __half* __restrict__ Bh) {
    const int total = 2 * QX + 2 * QW;
    for (int q = blockIdx.x * blockDim.x + threadIdx.x; q < total;
         q += gridDim.x * blockDim.x) {
        const float* src;
        __half* dst;
        int local, koff;
        bool interleave;
        if (q < 2 * QX) {
            dst = Ah; interleave = false;
            if (q < QX) { src = x; local = q; koff = 0; }
            else        { src = h; local = q - QX; koff = 1024; }
        } else {
            int r = q - 2 * QX;
            dst = Bh; interleave = true;
            if (r < QW) { src = W;  local = r; koff = 0; }
            else        { src = Uu; local = r - QW; koff = 1024; }
        }
        int row = local >> 8;
        int c   = (local & 255) * 4;
        // Touch-once data: streaming (evict-first) load + store, keep L2 clean
        float4 v = __ldcs((const float4*)&src[(size_t)row * 1024 + c]);
        __half2 h0 = __floats2half2_rn(v.x, v.y);
        __half2 h1 = __floats2half2_rn(v.z, v.w);
        uint2 packed = make_uint2(*(uint32_t*)&h0, *(uint32_t*)&h1);
        int drow = row;
        if (interleave) {                       // src row n = gate*1024 + hcol
            int gate = row >> 10, hcol = row & 1023;
            drow = hcol * 6 + gate;             // n' = h*6 + gate
        }
        __stcs((uint2*)&dst[(size_t)drow * KTOT + koff + c], packed);
    }
}

// ------------- fused GEMM (Z = Ah*Bh^T, K=2048, gate-4 midpoint split) + gate epilogue -------------
__global__ __launch_bounds__(256, 2)
void xlstm_fused_kernel(const __half* __restrict__ A, const __half* __restrict__ B,
                        const float* __restrict__ c_prev, const float* __restrict__ b_all,
                        float* __restrict__ out) {
    extern __shared__ char smem[];
    const uint32_t sbase = (uint32_t)__cvta_generic_to_shared(smem);

    const int tid  = threadIdx.x;
    const int warp = tid >> 5;
    const int lane = tid & 31;
    const int wm = warp & 1;        // 2 warps along M (64 rows)
    const int wn = warp >> 1;       // 4 warps along N (24 cols)
    const int g  = lane >> 2;       // 0..7
    const int tg = lane & 3;        // 0..3

    const int bm = blockIdx.y * BM;
    const int bnp = blockIdx.x * BN;     // interleaved-col offset
    const int h0 = blockIdx.x * 16;      // h block base

    const int lr = tid >> 1;        // 0..127
    const int lch = tid & 1;

    float acc[4][3][4];
    float wx4[4][2];
    #pragma unroll
    for (int mf = 0; mf < 4; mf++) {
        wx4[mf][0] = wx4[mf][1] = 0.0f;
        #pragma unroll
        for (int nf = 0; nf < 3; nf++)
            #pragma unroll
            for (int r = 0; r < 4; r++) acc[mf][nf][r] = 0.0f;
    }

    auto load_stage = [&](int i, int s) {
        const int k0 = i * BK;
        const uint32_t as = sbase + PIPE_OFF + s * STAGE_BYTES;
        const uint32_t bs = as + A_TILE_BYTES;
        const __half* ap = A + (size_t)(bm + lr) * KTOT + k0 + lch * 8;
        cp_async16(as + lr * ROWB + lch * 16,      ap);
        cp_async16(as + lr * ROWB + lch * 16 + 32, ap + 16);
        {   // B chunk tid (rows 0..63)
            int row = tid >> 2, ch = tid & 3;
            cp_async16(bs + row * ROWB + ch * 16,
                       B + (size_t)(bnp + row) * KTOT + k0 + ch * 8);
        }
        if (tid < 128) {   // B chunk tid+256 (rows 64..95)
            int cb = tid + 256;
            int row = cb >> 2, ch = cb & 3;
            cp_async16(bs + row * ROWB + ch * 16,
                       B + (size_t)(bnp + row) * KTOT + k0 + ch * 8);
        }
        asm volatile("cp.async.commit_group;\n" ::: "memory");
    };

    // One pipeline iteration; s/waitn/doload are compile-time literals at call sites,
    // so stage addressing constant-folds. Identical wait/commit/MMA order to R14.
    auto iter = [&](int i, int s, int waitn, bool doload) {
        if (waitn == 2)      asm volatile("cp.async.wait_group 2;\n" ::: "memory");
        else if (waitn == 1) asm volatile("cp.async.wait_group 1;\n" ::: "memory");
        else                 asm volatile("cp.async.wait_group 0;\n" ::: "memory");
        __syncthreads();

        if (doload) load_stage(i + 3, (i + 3) & 3);

        const uint4* as4 = (const uint4*)(smem + PIPE_OFF + s * STAGE_BYTES);
        const uint4* bs4 = (const uint4*)(smem + PIPE_OFF + s * STAGE_BYTES + A_TILE_BYTES);

        // k-remap: thread tg owns halves [8tg,8tg+8); (x,y) -> k16-step0 slots,
        // (z,w) -> step1. Same map for A and B => dot products unchanged.
        uint4 bq[3];
        #pragma unroll
        for (int nf = 0; nf < 3; nf++) {
            int c0 = wn * 24 + nf * 8 + g;
            bq[nf] = bs4[c0 * 4 + tg];
        }
        #pragma unroll
        for (int mf = 0; mf < 4; mf++) {
            int rr = wm * 64 + mf * 16 + g;
            uint4 lo = as4[rr * 4 + tg];
            uint4 hi = as4[(rr + 8) * 4 + tg];
            #pragma unroll
            for (int nf = 0; nf < 3; nf++) {
                asm volatile(
                    "mma.sync.aligned.m16n8k16.row.col.f32.f16.f16.f32 "
                    "{%0,%1,%2,%3}, {%4,%5,%6,%7}, {%8,%9}, {%0,%1,%2,%3};\n"
                    : "+f"(acc[mf][nf][0]), "+f"(acc[mf][nf][1]),
                      "+f"(acc[mf][nf][2]), "+f"(acc[mf][nf][3])
                    : "r"(lo.x), "r"(hi.x), "r"(lo.y), "r"(hi.y),
                      "r"(bq[nf].x), "r"(bq[nf].y));
            }
            #pragma unroll
            for (int nf = 0; nf < 3; nf++) {
                asm volatile(
                    "mma.sync.aligned.m16n8k16.row.col.f32.f16.f16.f32 "
                    "{%0,%1,%2,%3}, {%4,%5,%6,%7}, {%8,%9}, {%0,%1,%2,%3};\n"
                    : "+f"(acc[mf][nf][0]), "+f"(acc[mf][nf][1]),
                      "+f"(acc[mf][nf][2]), "+f"(acc[mf][nf][3])
                    : "r"(lo.z), "r"(hi.z), "r"(lo.w), "r"(hi.w),
                      "r"(bq[nf].z), "r"(bq[nf].w));
            }
        }
    };

    load_stage(0, 0);
    load_stage(1, 1);
    load_stage(2, 2);

    const int nf4 = (2 - tg + 3) % 3;    // the nf whose col-pair is (gate4, gate5)

    // First K half (x*W): i = 0..31
    #pragma unroll 1
    for (int ib = 0; ib < 32; ib += 4) {
        iter(ib + 0, 0, 2, true);
        iter(ib + 1, 1, 2, true);
        iter(ib + 2, 2, 2, true);
        iter(ib + 3, 3, 2, true);
    }

    // Midpoint (end of x*W half): save gate-4 cols (wx4) and reset them;
    // all other gates keep joint accumulation of wx+uh.
    #pragma unroll
    for (int nf = 0; nf < 3; nf++) {
        if (nf == nf4) {
            #pragma unroll
            for (int mf = 0; mf < 4; mf++) {
                wx4[mf][0] = acc[mf][nf][0];
                wx4[mf][1] = acc[mf][nf][2];
                acc[mf][nf][0] = 0.0f;
                acc[mf][nf][2] = 0.0f;
            }
        }
    }

    // Second K half (h*U): i = 32..59 grouped, 60..63 peeled (constant predicates)
    #pragma unroll 1
    for (int ib = 32; ib < 60; ib += 4) {
        iter(ib + 0, 0, 2, true);
        iter(ib + 1, 1, 2, true);
        iter(ib + 2, 2, 2, true);
        iter(ib + 3, 3, 2, true);
    }
    iter(60, 0, 2, true);     // loads stage for i=63
    iter(61, 1, 2, false);
    iter(62, 2, 1, false);
    iter(63, 3, 0, false);

    // -------- prefetch epilogue operands (overlap DRAM latency with smem exchange) --------
    const int hl   = tid & 15;
    const int bgrp = tid >> 4;             // 0..15, 8 rows each
    const int hg   = h0 + hl;
    float cpre[8];
    #pragma unroll
    for (int r = 0; r < 8; r++)
        cpre[r] = c_prev[(size_t)(bm + bgrp * 8 + r) * HDIM + hg];
    const float b0 = b_all[hg];
    const float b1 = b_all[1024 + hg];
    const float b2 = b_all[2048 + hg];
    const float b3 = b_all[3072 + hg];
    const float b4 = b_all[4096 + hg];
    const float b5 = b_all[5120 + hg];

    // -------- in-CTA gate epilogue --------
    __syncthreads();                       // all LDS of final stage consumed
    float* zs   = (float*)(smem + PIPE_OFF);        // [96][ZST]
    float* wx4s = zs + 96 * ZST;                    // [16][ZST]

    // h-local index of this thread's gate-4 column:
    // c = wn*24 + nf4*8 + 2tg  ->  h_local = wn*4 + (nf4*8 + 2tg)/6
    const int hl4 = wn * 4 + (nf4 * 8 + 2 * tg) / 6;

    #pragma unroll
    for (int mf = 0; mf < 4; mf++) {
        int row = wm * 64 + mf * 16 + g;
        #pragma unroll
        for (int nf = 0; nf < 3; nf++) {
            int col = wn * 24 + nf * 8 + 2 * tg;
            zs[col * ZST + row]           = acc[mf][nf][0];
            zs[(col + 1) * ZST + row]     = acc[mf][nf][1];
            zs[col * ZST + row + 8]       = acc[mf][nf][2];
            zs[(col + 1) * ZST + row + 8] = acc[mf][nf][3];
        }
        wx4s[hl4 * ZST + row]     = wx4[mf][0];
        wx4s[hl4 * ZST + row + 8] = wx4[mf][1];
    }
    __syncthreads();

    #pragma unroll
    for (int r = 0; r < 8; r++) {
        int b = bgrp * 8 + r;
        int bg = bm + b;
        float z0 = zs[(hl * 6 + 0) * ZST + b] + b0;
        float z1 = zs[(hl * 6 + 1) * ZST + b] + b1;
        float z2 = zs[(hl * 6 + 2) * ZST + b] + b2;
        float z3 = zs[(hl * 6 + 3) * ZST + b] + b3;
        float u4 = zs[(hl * 6 + 4) * ZST + b];          // uh4 (second half only)
        float z5 = zs[(hl * 6 + 5) * ZST + b] + b5;
        float w4 = wx4s[hl * ZST + b] + b4;             // wx4 + bias

        float ig = sigmoidf_(z0);
        float fg = sigmoidf_(z1);
        float og = sigmoidf_(z2);
        float gg = tanhf(z3);
        float m  = w4 * u4;
        float ag = sigmoidf_(z5);

        float cn = fg * cpre[r] + ig * gg + ag * m;
        float hn = og * tanhf(cn);

        out[(size_t)bg * HDIM + hg] = hn;
        out[(size_t)BDIM * HDIM + (size_t)bg * HDIM + hg] = cn;
    }
}

extern "C" void kernel_launch(void* const* d_in, const int* in_sizes, int n_in,
                              void* d_out, int out_size) {
    const float* x      = (const float*)d_in[0];
    const float* h_prev = (const float*)d_in[1];
    const float* c_prev = (const float*)d_in[2];
    const float* W_all  = (const float*)d_in[3];
    const float* b_all  = (const float*)d_in[4];
    const float* U_all  = (const float*)d_in[5];
    float* out = (float*)d_out;

    __half *pAh = nullptr, *pBh = nullptr;
    cudaGetSymbolAddress((void**)&pAh, g_Ah);
    cudaGetSymbolAddress((void**)&pBh, g_Bh);

    // Grid-stride conversion, exact-fill launch (8 CTAs/SM x 148 SMs)
    conv_all_kernel<<<1184, 256>>>(x, h_prev, W_all, U_all, pAh, pBh);

    cudaFuncSetAttribute(xlstm_fused_kernel,
                         cudaFuncAttributeMaxDynamicSharedMemorySize, SMEM_TOTAL);

    dim3 grid(HDIM / 16, BDIM / BM);   // 64 x 32
    xlstm_fused_kernel<<<grid, 256, SMEM_TOTAL>>>(pAh, pBh, c_prev, b_all, out);
}

// round 17
// speedup vs baseline: 1.2740x; 1.0028x over previous
#include <cuda_runtime.h>
#include <cuda_fp16.h>
#include <cstdint>
#include <cstddef>

// Problem dims
#define BDIM 4096
#define HDIM 1024
#define NDIM 6144           // 6 gates * H (gate-interleaved: n' = h*6 + gate)
#define KTOT 2048           // joint K (x|h concatenated)

// GEMM tiling: CTA 128x96 (16 h-cols x 6 gates), 8 warps of 64x24, 2 CTAs/SM
#define BM 128
#define BN 96
#define BK 32               // halves per k-chunk = 64B rows (conflict-free LDS.128)
#define ROWB 64
#define A_TILE_BYTES (128 * ROWB)        // 8192
#define B_TILE_BYTES (96 * ROWB)         // 6144
#define STAGE_BYTES (A_TILE_BYTES + B_TILE_BYTES)   // 14336
#define NSTAGE 4
#define NK 64               // 2048 / 32
#define PIPE_OFF 512
#define ZST 132             // zs row stride (floats) — conflict-free STS
#define EPI_BYTES ((96 + 16) * ZST * 4)  // 59136
#define SMEM_TOTAL (PIPE_OFF + (EPI_BYTES > NSTAGE*STAGE_BYTES ? EPI_BYTES : NSTAGE*STAGE_BYTES))

// Scratch
__device__ __half g_Ah[(size_t)BDIM * KTOT];   // [x | h] fp16
__device__ __half g_Bh[(size_t)NDIM * KTOT];   // gate-interleaved [W | U] fp16

__device__ __forceinline__ void cp_async16(uint32_t smem_addr, const void* gmem_ptr) {
    asm volatile("cp.async.cg.shared.global [%0], [%1], 16;\n" :: "r"(smem_addr), "l"(gmem_ptr));
}

__device__ __forceinline__ float sigmoidf_(float z) { return 1.0f / (1.0f + expf(-z)); }

// ---------------- merged fp32 -> fp16 conversion (8 floats/thread, streaming) ----------------
// x -> Ah[:,0:1024], h -> Ah[:,1024:], W -> Bh[h*6+g, 0:1024], U -> Bh[h*6+g, 1024:]
// Group = 8 consecutive floats of one source row -> one 16 B fp16 store.
#define GX (BDIM * 128)     // 8-float groups per [4096,1024] tensor
#define GW (NDIM * 128)
__global__ __launch_bounds__(256)
void conv_all_kernel(const float* __restrict__ x, const float* __restrict__ h,
                     const float* __restrict__ W, const float* __restrict__ Uu,
                     __half* __restrict__ Ah, __half* __restrict__ Bh) {
    const int total = 2 * GX + 2 * GW;
    for (int q = blockIdx.x * blockDim.x + threadIdx.x; q < total;
         q += gridDim.x * blockDim.x) {
        const float* src;
        __half* dst;
        int local, koff;
        bool interleave;
        if (q < 2 * GX) {
            dst = Ah; interleave = false;
            if (q < GX) { src = x; local = q; koff = 0; }
            else        { src = h; local = q - GX; koff = 1024; }
        } else {
            int r = q - 2 * GX;
            dst = Bh; interleave = true;
            if (r < GW) { src = W;  local = r; koff = 0; }
            else        { src = Uu; local = r - GW; koff = 1024; }
        }
        int row = local >> 7;           // source row
        int c   = (local & 127) * 8;    // column of 8-float group
        const float4* sp = (const float4*)&src[(size_t)row * 1024 + c];
        float4 v0 = __ldcs(sp);
        float4 v1 = __ldcs(sp + 1);
        __half2 h0 = __floats2half2_rn(v0.x, v0.y);
        __half2 h1 = __floats2half2_rn(v0.z, v0.w);
        __half2 h2 = __floats2half2_rn(v1.x, v1.y);
        __half2 h3 = __floats2half2_rn(v1.z, v1.w);
        uint4 packed = make_uint4(*(uint32_t*)&h0, *(uint32_t*)&h1,
                                  *(uint32_t*)&h2, *(uint32_t*)&h3);
        int drow = row;
        if (interleave) {               // src row n = gate*1024 + hcol
            int gate = row >> 10, hcol = row & 1023;
            drow = hcol * 6 + gate;     // n' = h*6 + gate
        }
        __stcs((uint4*)&dst[(size_t)drow * KTOT + koff + c], packed);
    }
}

// ------------- fused GEMM (Z = Ah*Bh^T, K=2048, gate-4 midpoint split) + gate epilogue -------------
__global__ __launch_bounds__(256, 2)
void xlstm_fused_kernel(const __half* __restrict__ A, const __half* __restrict__ B,
                        const float* __restrict__ c_prev, const float* __restrict__ b_all,
                        float* __restrict__ out) {
    extern __shared__ char smem[];
    const uint32_t sbase = (uint32_t)__cvta_generic_to_shared(smem);

    const int tid  = threadIdx.x;
    const int warp = tid >> 5;
    const int lane = tid & 31;
    const int wm = warp & 1;        // 2 warps along M (64 rows)
    const int wn = warp >> 1;       // 4 warps along N (24 cols)
    const int g  = lane >> 2;       // 0..7
    const int tg = lane & 3;        // 0..3

    const int bm = blockIdx.y * BM;
    const int bnp = blockIdx.x * BN;     // interleaved-col offset
    const int h0 = blockIdx.x * 16;      // h block base

    const int lr = tid >> 1;        // 0..127
    const int lch = tid & 1;

    float acc[4][3][4];
    float wx4[4][2];
    #pragma unroll
    for (int mf = 0; mf < 4; mf++) {
        wx4[mf][0] = wx4[mf][1] = 0.0f;
        #pragma unroll
        for (int nf = 0; nf < 3; nf++)
            #pragma unroll
            for (int r = 0; r < 4; r++) acc[mf][nf][r] = 0.0f;
    }

    auto load_stage = [&](int i, int s) {
        const int k0 = i * BK;
        const uint32_t as = sbase + PIPE_OFF + s * STAGE_BYTES;
        const uint32_t bs = as + A_TILE_BYTES;
        const __half* ap = A + (size_t)(bm + lr) * KTOT + k0 + lch * 8;
        cp_async16(as + lr * ROWB + lch * 16,      ap);
        cp_async16(as + lr * ROWB + lch * 16 + 32, ap + 16);
        {   // B chunk tid (rows 0..63)
            int row = tid >> 2, ch = tid & 3;
            cp_async16(bs + row * ROWB + ch * 16,
                       B + (size_t)(bnp + row) * KTOT + k0 + ch * 8);
        }
        if (tid < 128) {   // B chunk tid+256 (rows 64..95)
            int cb = tid + 256;
            int row = cb >> 2, ch = cb & 3;
            cp_async16(bs + row * ROWB + ch * 16,
                       B + (size_t)(bnp + row) * KTOT + k0 + ch * 8);
        }
        asm volatile("cp.async.commit_group;\n" ::: "memory");
    };

    // One pipeline iteration; s/waitn/doload are compile-time literals at call sites,
    // so stage addressing constant-folds. Identical wait/commit/MMA order to R16.
    auto iter = [&](int i, int s, int waitn, bool doload) {
        if (waitn == 2)      asm volatile("cp.async.wait_group 2;\n" ::: "memory");
        else if (waitn == 1) asm volatile("cp.async.wait_group 1;\n" ::: "memory");
        else                 asm volatile("cp.async.wait_group 0;\n" ::: "memory");
        __syncthreads();

        if (doload) load_stage(i + 3, (i + 3) & 3);

        const uint4* as4 = (const uint4*)(smem + PIPE_OFF + s * STAGE_BYTES);
        const uint4* bs4 = (const uint4*)(smem + PIPE_OFF + s * STAGE_BYTES + A_TILE_BYTES);

        // k-remap: thread tg owns halves [8tg,8tg+8); (x,y) -> k16-step0 slots,
        // (z,w) -> step1. Same map for A and B => dot products unchanged.
        uint4 bq[3];
        #pragma unroll
        for (int nf = 0; nf < 3; nf++) {
            int c0 = wn * 24 + nf * 8 + g;
            bq[nf] = bs4[c0 * 4 + tg];
        }
        #pragma unroll
        for (int mf = 0; mf < 4; mf++) {
            int rr = wm * 64 + mf * 16 + g;
            uint4 lo = as4[rr * 4 + tg];
            uint4 hi = as4[(rr + 8) * 4 + tg];
            #pragma unroll
            for (int nf = 0; nf < 3; nf++) {
                asm volatile(
                    "mma.sync.aligned.m16n8k16.row.col.f32.f16.f16.f32 "
                    "{%0,%1,%2,%3}, {%4,%5,%6,%7}, {%8,%9}, {%0,%1,%2,%3};\n"
                    : "+f"(acc[mf][nf][0]), "+f"(acc[mf][nf][1]),
                      "+f"(acc[mf][nf][2]), "+f"(acc[mf][nf][3])
                    : "r"(lo.x), "r"(hi.x), "r"(lo.y), "r"(hi.y),
                      "r"(bq[nf].x), "r"(bq[nf].y));
            }
            #pragma unroll
            for (int nf = 0; nf < 3; nf++) {
                asm volatile(
                    "mma.sync.aligned.m16n8k16.row.col.f32.f16.f16.f32 "
                    "{%0,%1,%2,%3}, {%4,%5,%6,%7}, {%8,%9}, {%0,%1,%2,%3};\n"
                    : "+f"(acc[mf][nf][0]), "+f"(acc[mf][nf][1]),
                      "+f"(acc[mf][nf][2]), "+f"(acc[mf][nf][3])
                    : "r"(lo.z), "r"(hi.z), "r"(lo.w), "r"(hi.w),
                      "r"(bq[nf].z), "r"(bq[nf].w));
            }
        }
    };

    load_stage(0, 0);
    load_stage(1, 1);
    load_stage(2, 2);

    const int nf4 = (2 - tg + 3) % 3;    // the nf whose col-pair is (gate4, gate5)

    // First K half (x*W): i = 0..31
    #pragma unroll 1
    for (int ib = 0; ib < 32; ib += 4) {
        iter(ib + 0, 0, 2, true);
        iter(ib + 1, 1, 2, true);
        iter(ib + 2, 2, 2, true);
        iter(ib + 3, 3, 2, true);
    }

    // Midpoint (end of x*W half): save gate-4 cols (wx4) and reset them;
    // all other gates keep joint accumulation of wx+uh.
    #pragma unroll
    for (int nf = 0; nf < 3; nf++) {
        if (nf == nf4) {
            #pragma unroll
            for (int mf = 0; mf < 4; mf++) {
                wx4[mf][0] = acc[mf][nf][0];
                wx4[mf][1] = acc[mf][nf][2];
                acc[mf][nf][0] = 0.0f;
                acc[mf][nf][2] = 0.0f;
            }
        }
    }

    // Second K half (h*U): i = 32..59 grouped, 60..63 peeled (constant predicates)
    #pragma unroll 1
    for (int ib = 32; ib < 60; ib += 4) {
        iter(ib + 0, 0, 2, true);
        iter(ib + 1, 1, 2, true);
        iter(ib + 2, 2, 2, true);
        iter(ib + 3, 3, 2, true);
    }
    iter(60, 0, 2, true);     // loads stage for i=63
    iter(61, 1, 2, false);
    iter(62, 2, 1, false);
    iter(63, 3, 0, false);

    // -------- prefetch epilogue operands (overlap DRAM latency with smem exchange) --------
    const int hl   = tid & 15;
    const int bgrp = tid >> 4;             // 0..15, 8 rows each
    const int hg   = h0 + hl;
    float cpre[8];
    #pragma unroll
    for (int r = 0; r < 8; r++)
        cpre[r] = c_prev[(size_t)(bm + bgrp * 8 + r) * HDIM + hg];
    const float b0 = b_all[hg];
    const float b1 = b_all[1024 + hg];
    const float b2 = b_all[2048 + hg];
    const float b3 = b_all[3072 + hg];
    const float b4 = b_all[4096 + hg];
    const float b5 = b_all[5120 + hg];

    // -------- in-CTA gate epilogue --------
    __syncthreads();                       // all LDS of final stage consumed
    float* zs   = (float*)(smem + PIPE_OFF);        // [96][ZST]
    float* wx4s = zs + 96 * ZST;                    // [16][ZST]

    // h-local index of this thread's gate-4 column:
    // c = wn*24 + nf4*8 + 2tg  ->  h_local = wn*4 + (nf4*8 + 2tg)/6
    const int hl4 = wn * 4 + (nf4 * 8 + 2 * tg) / 6;

    #pragma unroll
    for (int mf = 0; mf < 4; mf++) {
        int row = wm * 64 + mf * 16 + g;
        #pragma unroll
        for (int nf = 0; nf < 3; nf++) {
            int col = wn * 24 + nf * 8 + 2 * tg;
            zs[col * ZST + row]           = acc[mf][nf][0];
            zs[(col + 1) * ZST + row]     = acc[mf][nf][1];
            zs[col * ZST + row + 8]       = acc[mf][nf][2];
            zs[(col + 1) * ZST + row + 8] = acc[mf][nf][3];
        }
        wx4s[hl4 * ZST + row]     = wx4[mf][0];
        wx4s[hl4 * ZST + row + 8] = wx4[mf][1];
    }
    __syncthreads();

    #pragma unroll
    for (int r = 0; r < 8; r++) {
        int b = bgrp * 8 + r;
        int bg = bm + b;
        float z0 = zs[(hl * 6 + 0) * ZST + b] + b0;
        float z1 = zs[(hl * 6 + 1) * ZST + b] + b1;
        float z2 = zs[(hl * 6 + 2) * ZST + b] + b2;
        float z3 = zs[(hl * 6 + 3) * ZST + b] + b3;
        float u4 = zs[(hl * 6 + 4) * ZST + b];          // uh4 (second half only)
        float z5 = zs[(hl * 6 + 5) * ZST + b] + b5;
        float w4 = wx4s[hl * ZST + b] + b4;             // wx4 + bias

        float ig = sigmoidf_(z0);
        float fg = sigmoidf_(z1);
        float og = sigmoidf_(z2);
        float gg = tanhf(z3);
        float m  = w4 * u4;
        float ag = sigmoidf_(z5);

        float cn = fg * cpre[r] + ig * gg + ag * m;
        float hn = og * tanhf(cn);

        out[(size_t)bg * HDIM + hg] = hn;
        out[(size_t)BDIM * HDIM + (size_t)bg * HDIM + hg] = cn;
    }
}

extern "C" void kernel_launch(void* const* d_in, const int* in_sizes, int n_in,
                              void* d_out, int out_size) {
    const float* x      = (const float*)d_in[0];
    const float* h_prev = (const float*)d_in[1];
    const float* c_prev = (const float*)d_in[2];
    const float* W_all  = (const float*)d_in[3];
    const float* b_all  = (const float*)d_in[4];
    const float* U_all  = (const float*)d_in[5];
    float* out = (float*)d_out;

    __half *pAh = nullptr, *pBh = nullptr;
    cudaGetSymbolAddress((void**)&pAh, g_Ah);
    cudaGetSymbolAddress((void**)&pBh, g_Bh);

    // Grid-stride conversion, exact-fill launch (8 CTAs/SM x 148 SMs)
    conv_all_kernel<<<1184, 256>>>(x, h_prev, W_all, U_all, pAh, pBh);

    cudaFuncSetAttribute(xlstm_fused_kernel,
                         cudaFuncAttributeMaxDynamicSharedMemorySize, SMEM_TOTAL);

    dim3 grid(HDIM / 16, BDIM / BM);   // 64 x 32
    xlstm_fused_kernel<<<grid, 256, SMEM_TOTAL>>>(pAh, pBh, c_prev, b_all, out);
}